// round 2
// baseline (speedup 1.0000x reference)
#include <cuda_runtime.h>
#include <math.h>

#define B_   16
#define N_   2048
#define K_   16
#define EPS_ 1e-8f

// Output layout (tuple flattened in order):
//   psi_prime : B*N*2  floats  @ 0
//   features  : B*N*5  floats  @ 65536
//   knn_idx   : B*N*16 floats  @ 229376
#define PSI_OFF  0
#define FEAT_OFF (B_ * N_ * 2)
#define KNN_OFF  (B_ * N_ * 2 + B_ * N_ * 5)

// ---------------------------------------------------------------------------
// Kernel 1: features + encoder (tiny MLP). One thread per (b, n) point.
// ---------------------------------------------------------------------------
__global__ void encode_kernel(const float* __restrict__ coords,
                              const float* __restrict__ demands,
                              const float* __restrict__ capacity,
                              const float* __restrict__ Wa,
                              const float* __restrict__ ba,
                              const float* __restrict__ W1,
                              const float* __restrict__ b1,
                              const float* __restrict__ W2,
                              const float* __restrict__ b2,
                              float* __restrict__ out)
{
    int b = blockIdx.y;
    int n = blockIdx.x * blockDim.x + threadIdx.x;
    if (n >= N_) return;

    __shared__ float sWa[10], sba[2], sW1[80], sb1[16], sW2[16], sb2_s;
    int t = threadIdx.x;
    if (t < 10) sWa[t] = Wa[t];
    if (t < 2)  sba[t] = ba[t];
    if (t < 80) sW1[t] = W1[t];
    if (t < 16) { sb1[t] = b1[t]; sW2[t] = W2[t]; }
    if (t == 0) sb2_s = b2[0];
    __syncthreads();

    const float* cp = coords + ((long long)b * N_ + n) * 2;
    float x = cp[0], y = cp[1];
    float dx0 = coords[(long long)b * N_ * 2 + 0];
    float dy0 = coords[(long long)b * N_ * 2 + 1];
    float rx = x - dx0, ry = y - dy0;
    float dist = sqrtf(rx * rx + ry * ry + EPS_);
    float ang  = atan2f(ry, rx);
    float dem  = demands[(long long)b * N_ + n] / capacity[b];

    float f0 = x, f1 = y, f2 = dem, f3 = dist, f4 = ang;

    float* fo = out + FEAT_OFF + ((long long)b * N_ + n) * 5;
    fo[0] = f0; fo[1] = f1; fo[2] = f2; fo[3] = f3; fo[4] = f4;

    float p0 = sba[0] + f0*sWa[0] + f1*sWa[1] + f2*sWa[2] + f3*sWa[3] + f4*sWa[4];
    float p1 = sba[1] + f0*sWa[5] + f1*sWa[6] + f2*sWa[7] + f3*sWa[8] + f4*sWa[9];
    float nrm = sqrtf(p0 * p0 + p1 * p1);
    float inv = 1.0f / (nrm + EPS_);
    p0 *= inv; p1 *= inv;

    float theta = sb2_s;
    #pragma unroll
    for (int h = 0; h < 16; ++h) {
        const float* w = sW1 + h * 5;
        float a = sb1[h] + f0*w[0] + f1*w[1] + f2*w[2] + f3*w[3] + f4*w[4];
        theta += tanhf(a) * sW2[h];
    }
    float c = cosf(theta), s = sinf(theta);

    float* po = out + PSI_OFF + ((long long)b * N_ + n) * 2;
    po[0] = c * p0 - s * p1;
    po[1] = s * p0 + c * p1;
}

// ---------------------------------------------------------------------------
// Kernel 2: KNN top-16. One thread per query; candidates staged in SMEM and
// read as warp-uniform broadcasts.
//
// Arithmetic emulates the reference's gemm lowering bit-exactly:
//   dot = fma(y_q*y_j, rn(x_q*x_j))   <- gemm k-loop FMA accumulation
//   d2  = rn( rn(sq_q + sq_j) - rn(2*dot) )
// so top-k ordering matches the reference at near-ties.
// ---------------------------------------------------------------------------
__global__ void __launch_bounds__(256, 1)
knn_kernel(const float* __restrict__ coords, float* __restrict__ out_knn)
{
    __shared__ float sx[N_], sy[N_], ssq[N_];
    int b = blockIdx.y;
    const float* cb = coords + (long long)b * N_ * 2;

    for (int i = threadIdx.x; i < N_; i += blockDim.x) {
        float x = cb[2 * i], y = cb[2 * i + 1];
        sx[i] = x; sy[i] = y;
        // jnp.sum(coords*coords): elementwise products rounded, then summed
        ssq[i] = __fadd_rn(__fmul_rn(x, x), __fmul_rn(y, y));
    }
    __syncthreads();

    int q = blockIdx.x * blockDim.x + threadIdx.x;
    float xq = sx[q], yq = sy[q], sqq = ssq[q];

    float bd[K_];
    int   bi[K_];
    #pragma unroll
    for (int k = 0; k < K_; ++k) { bd[k] = 3.0e30f; bi[k] = 0; }

    for (int j = 0; j < N_; ++j) {
        // gemm-style FMA dot: acc = rn(x*x'); acc = fma(y, y', acc)
        float dot = __fmaf_rn(yq, sy[j], __fmul_rn(xq, sx[j]));
        float d2  = __fsub_rn(__fadd_rn(sqq, ssq[j]), __fmul_rn(2.0f, dot));
        if (j == q) d2 = 2.0e30f;  // self-exclusion (ref adds 1e10 on diagonal)

        if (d2 < bd[K_ - 1]) {
            // statically-unrolled sorted insert; strict '<' reproduces the
            // stable tie-break of jax.lax.top_k (earlier index ranks first).
            #pragma unroll
            for (int k = K_ - 1; k > 0; --k) {
                bool shift = d2 < bd[k - 1];
                float sd = shift ? bd[k - 1] : d2;
                int   si = shift ? bi[k - 1] : j;
                bool place = d2 < bd[k];
                bd[k] = place ? sd : bd[k];
                bi[k] = place ? si : bi[k];
            }
            if (d2 < bd[0]) { bd[0] = d2; bi[0] = j; }
        }
    }

    float* o = out_knn + ((long long)b * N_ + q) * K_;
    #pragma unroll
    for (int k = 0; k < K_; ++k) o[k] = (float)bi[k];
}

// ---------------------------------------------------------------------------
extern "C" void kernel_launch(void* const* d_in, const int* in_sizes, int n_in,
                              void* d_out, int out_size)
{
    const float* coords   = (const float*)d_in[0];
    const float* demands  = (const float*)d_in[1];
    const float* capacity = (const float*)d_in[2];
    const float* Wa       = (const float*)d_in[3];
    const float* ba       = (const float*)d_in[4];
    const float* W1       = (const float*)d_in[5];
    const float* b1       = (const float*)d_in[6];
    const float* W2       = (const float*)d_in[7];
    const float* b2       = (const float*)d_in[8];
    float* out = (float*)d_out;

    dim3 blk(256);
    dim3 grd(N_ / 256, B_);

    encode_kernel<<<grd, blk>>>(coords, demands, capacity,
                                Wa, ba, W1, b1, W2, b2, out);
    knn_kernel<<<grd, blk>>>(coords, out + KNN_OFF);
}